// round 4
// baseline (speedup 1.0000x reference)
#include <cuda_runtime.h>

#define RR 1040      // B*S segment rows
#define SS 65        // segments per batch
#define BB 16        // batch
#define DD 128       // feature dim
#define WW 256       // candidate positions per segment
#define TT 2176      // MAX_LEN_PAD (x time dim)
#define OUT_T 2048   // MAX_LEN_SEQ

// Scratch (allocation-free requirement -> __device__ globals)
__device__ int g_count[RR];
__device__ int g_offset[RR];
__device__ int g_rowstart[RR];
__device__ int g_meta[2];   // [0]=total, [1]=L

// ---------------------------------------------------------------------------
// Kernel 1: per-batch segment offsets + per-row masked counts.
// Mask math replicates the JAX fp32 ops bit-exactly:
//   idx_scaled = w / sc           (IEEE RN division)
//   idx_fl     = floor(idx_scaled)
//   mask1: idx_fl < len_seg - 1
//   mask2: idx_fl + offset < len_seq - 1   <=>  idx_fl < (len_seq-1) - offset
// (all thresholds are exact integers in fp32, so fminf of the two is exact)
// ---------------------------------------------------------------------------
__global__ void k_setup(const float* __restrict__ scales,
                        const int*   __restrict__ len_seq,
                        const int*   __restrict__ len_seg_raw) {
    __shared__ int sseg[SS];
    __shared__ int soff[SS];
    const int b   = blockIdx.x;
    const int tid = threadIdx.x;

    if (tid < SS) sseg[tid] = len_seg_raw[b * SS + tid] + 32;  // +MIN_LEN_SEG
    __syncthreads();
    if (tid == 0) {
        int run = 0;
        #pragma unroll 1
        for (int s = 0; s < SS; s++) { soff[s] = run; run += sseg[s]; }
    }
    __syncthreads();

    const int lane = tid & 31;
    const int wid  = tid >> 5;
    const int lseq = len_seq[b];

    for (int s = wid; s < SS; s += 8) {
        const int   r   = b * SS + s;
        const float sc  = scales[r] + 0.5f;
        const int   off = soff[s];
        const float lim = fminf((float)(sseg[s] - 1),
                                (float)(lseq - 1) - (float)off);
        int c = 0;
        #pragma unroll
        for (int k = 0; k < 8; k++) {
            const int   w   = lane + k * 32;
            const float ifl = floorf(__fdiv_rn((float)w, sc));
            c += (ifl < lim) ? 1 : 0;
        }
        c = __reduce_add_sync(0xffffffffu, c);
        if (lane == 0) { g_count[r] = c; g_offset[r] = off; }
    }
}

// ---------------------------------------------------------------------------
// Kernel 2: single-block exclusive scan of 1040 counts -> rowstart, total, L.
// ---------------------------------------------------------------------------
__global__ void k_scan() {
    const int ITEMS = 5;                 // 256 * 5 = 1280 >= 1040
    __shared__ int s_wsum[8];
    __shared__ int s_wbase[8];
    const int tid  = threadIdx.x;
    const int lane = tid & 31;
    const int wid  = tid >> 5;
    const int base_idx = tid * ITEMS;

    int loc[ITEMS];
    int run = 0;
    #pragma unroll
    for (int j = 0; j < ITEMS; j++) {
        const int idx = base_idx + j;
        const int c   = (idx < RR) ? g_count[idx] : 0;
        loc[j] = run; run += c;
    }
    int inc = run;
    #pragma unroll
    for (int d = 1; d < 32; d <<= 1) {
        const int n = __shfl_up_sync(0xffffffffu, inc, d);
        if (lane >= d) inc += n;
    }
    const int texcl = inc - run;
    if (lane == 31) s_wsum[wid] = inc;
    __syncthreads();
    if (tid == 0) {
        int acc = 0;
        #pragma unroll
        for (int i = 0; i < 8; i++) { s_wbase[i] = acc; acc += s_wsum[i]; }
        g_meta[0] = acc;
        g_meta[1] = acc / BB;     // L = total // B
    }
    __syncthreads();
    const int base = s_wbase[wid] + texcl;
    #pragma unroll
    for (int j = 0; j < ITEMS; j++) {
        const int idx = base_idx + j;
        if (idx < RR) g_rowstart[idx] = base + loc[j];
    }
}

// ---------------------------------------------------------------------------
// Kernel 3: zero-fill out where t >= L (d_out is poisoned to 0xAA).
// Writes only t >= L, disjoint from k_main's writes (t < L).
// ---------------------------------------------------------------------------
__global__ void k_zero(float* __restrict__ out) {
    const int L = g_meta[1];
    const unsigned i = blockIdx.x * blockDim.x + threadIdx.x; // float4 index
    const int t = (int)((i >> 5) & (OUT_T - 1));              // DD/4 = 32 float4/row
    if (t >= L) {
        ((float4*)out)[i] = make_float4(0.f, 0.f, 0.f, 0.f);
    }
}

// ---------------------------------------------------------------------------
// Kernel 4: gather + lerp + scatter. One block per segment row, one warp per
// surviving (r, w) entry, float4 per lane across D=128.
// Global compacted slot p = rowstart[r] + w  ->  out[p / L, p % L].
// ---------------------------------------------------------------------------
__global__ void __launch_bounds__(256, 8)
k_main(const float* __restrict__ x,
       const float* __restrict__ scales,
       float* __restrict__ out) {
    const int r     = blockIdx.x;
    const int count = g_count[r];
    const int L     = g_meta[1];
    if (count == 0 || L <= 0) return;

    const int lane = threadIdx.x & 31;
    const int wid  = threadIdx.x >> 5;

    const float sc  = scales[r] + 0.5f;
    const int   off = g_offset[r];
    const int   rs  = g_rowstart[r];
    const int   b_in = r / SS;
    const float4* xb = (const float4*)(x + (size_t)b_in * TT * DD);

    for (int w = wid; w < count; w += 8) {
        const float ws  = __fdiv_rn((float)w, sc);
        const float ifl = floorf(ws);
        const float lam = ws - ifl;

        int i0 = (int)ifl + off;
        i0 = min(max(i0, 0), TT - 1);
        const int i1 = min(i0 + 1, TT - 1);

        const int p  = rs + w;
        const int bo = p / L;
        const int t  = p - bo * L;
        if (bo < BB && t < OUT_T) {
            const float4 a = xb[i0 * (DD / 4) + lane];
            const float4 c = xb[i1 * (DD / 4) + lane];
            float4 y;
            y.x = (1.0f - lam) * a.x + lam * c.x;
            y.y = (1.0f - lam) * a.y + lam * c.y;
            y.z = (1.0f - lam) * a.z + lam * c.z;
            y.w = (1.0f - lam) * a.w + lam * c.w;
            ((float4*)out)[((size_t)bo * OUT_T + t) * (DD / 4) + lane] = y;
        }
    }
}

// ---------------------------------------------------------------------------
extern "C" void kernel_launch(void* const* d_in, const int* in_sizes, int n_in,
                              void* d_out, int out_size) {
    const float* x           = (const float*)d_in[0];
    const float* scales      = (const float*)d_in[1];
    const int*   len_seq     = (const int*)d_in[2];
    const int*   len_seg_raw = (const int*)d_in[3];
    float*       out         = (float*)d_out;

    k_setup<<<BB, 256>>>(scales, len_seq, len_seg_raw);
    k_scan<<<1, 256>>>();
    k_zero<<<(BB * OUT_T * (DD / 4)) / 256, 256>>>(out);
    k_main<<<RR, 256>>>(x, scales, out);
}

// round 6
// speedup vs baseline: 1.3874x; 1.3874x over previous
#include <cuda_runtime.h>

#define RR 1040      // B*S segment rows
#define SS 65        // segments per batch
#define BB 16        // batch
#define DD 128       // feature dim
#define WW 256       // candidate positions per segment
#define TT 2176      // MAX_LEN_PAD (x time dim)
#define OUT_T 2048   // MAX_LEN_SEQ
#define ZBLK 512     // zero-fill blocks appended to k_main grid

// Scratch (allocation-free requirement -> __device__ globals)
__device__ int g_count[RR];
__device__ int g_offset[RR];
__device__ int g_rowstart[RR];
__device__ int g_meta[2];   // [0]=total, [1]=L

// ---------------------------------------------------------------------------
// k_prep: ONE block, 1024 threads. Does everything the old k_setup + k_scan
// did:
//   - per-batch segment-length prefix (offsets)
//   - per-row masked count. The mask is a prefix in w (IEEE __fdiv_rn is
//     monotone non-decreasing in the numerator, and the thresholds are
//     integer-valued floats, so  floor(w/sc) < lim  <=>  w/sc < lim), so an
//     8-step binary search with the EXACT same fp32 predicate reproduces the
//     JAX mask count bit-for-bit.
//   - 1040-wide exclusive scan -> rowstart, total, L = total // B
// ---------------------------------------------------------------------------
__global__ void __launch_bounds__(1024) k_prep(const float* __restrict__ scales,
                                               const int*   __restrict__ len_seq,
                                               const int*   __restrict__ len_seg_raw) {
    __shared__ int sseg[RR];
    __shared__ int soff[RR];
    __shared__ int s_wsum[32];
    __shared__ int s_wbase[32];
    const int tid  = threadIdx.x;
    const int lane = tid & 31;
    const int wid  = tid >> 5;

    for (int i = tid; i < RR; i += 1024) sseg[i] = len_seg_raw[i] + 32; // +MIN_LEN_SEG
    __syncthreads();
    if (tid < BB) {                       // per-batch segment offset prefix
        int run = 0;
        const int base = tid * SS;
        #pragma unroll 1
        for (int s = 0; s < SS; s++) { soff[base + s] = run; run += sseg[base + s]; }
    }
    __syncthreads();

    // Two ordered rows per thread -> counts via binary search, local scan.
    int cnt[2], loc[2];
    int run = 0;
    #pragma unroll
    for (int j = 0; j < 2; j++) {
        const int r = tid * 2 + j;
        int c = 0;
        if (r < RR) {
            const float sc  = scales[r] + 0.5f;
            const int   off = soff[r];
            const int   ls  = len_seq[r / SS];
            const float lim = fminf((float)(sseg[r] - 1),
                                    (float)(ls - 1) - (float)off);
            int lo = 0, hi = WW;          // pred(w) = __fdiv_rn(w,sc) < lim, prefix-true
            #pragma unroll
            for (int it = 0; it < 8; it++) {
                const int mid = (lo + hi) >> 1;
                if (__fdiv_rn((float)mid, sc) < lim) lo = mid + 1; else hi = mid;
            }
            c = lo;
        }
        loc[j] = run; run += c; cnt[j] = c;
    }
    // warp inclusive scan of per-thread sums
    int inc = run;
    #pragma unroll
    for (int d = 1; d < 32; d <<= 1) {
        const int n = __shfl_up_sync(0xffffffffu, inc, d);
        if (lane >= d) inc += n;
    }
    const int texcl = inc - run;
    if (lane == 31) s_wsum[wid] = inc;
    __syncthreads();
    if (tid == 0) {
        int acc = 0;
        #pragma unroll
        for (int i = 0; i < 32; i++) { s_wbase[i] = acc; acc += s_wsum[i]; }
        g_meta[0] = acc;
        g_meta[1] = acc / BB;             // L = total // B
    }
    __syncthreads();
    const int base = s_wbase[wid] + texcl;
    #pragma unroll
    for (int j = 0; j < 2; j++) {
        const int r = tid * 2 + j;
        if (r < RR) {
            g_rowstart[r] = base + loc[j];
            g_count[r]    = cnt[j];
            g_offset[r]   = soff[r];
        }
    }
}

// ---------------------------------------------------------------------------
// k_main: blocks [0, RR) -> gather+lerp+scatter, one warp per 4 consecutive
// entries (8 LDG.128 in flight before first use -> 4x MLP vs previous rev).
// Blocks [RR, RR+ZBLK) -> predicated zero-fill of the t >= L tail
// (d_out is poisoned to 0xAA; writes are disjoint from the main path).
// ---------------------------------------------------------------------------
__global__ void __launch_bounds__(256)
k_main(const float* __restrict__ x,
       const float* __restrict__ scales,
       float* __restrict__ out) {
    const int bx = blockIdx.x;
    const int L  = g_meta[1];

    if (bx >= RR) {                       // ---- zero-fill tail ----
        if (L >= OUT_T || L <= 0) return;
        const unsigned base = (unsigned)(bx - RR) * 256u + threadIdx.x;
        const float4 z = make_float4(0.f, 0.f, 0.f, 0.f);
        #pragma unroll
        for (int j = 0; j < 8; j++) {
            const unsigned i = base + (unsigned)j * (ZBLK * 256u); // 1,048,576 float4 total
            const int t = (int)((i >> 5) & (OUT_T - 1));           // 32 float4 per row
            if (t >= L) ((float4*)out)[i] = z;
        }
        return;
    }

    const int count = g_count[bx];
    if (count == 0 || L <= 0) return;

    const int lane = threadIdx.x & 31;
    const int wid  = threadIdx.x >> 5;

    const float sc  = scales[bx] + 0.5f;
    const int   off = g_offset[bx];
    const int   rs  = g_rowstart[bx];
    const float4* xb = (const float4*)x + (size_t)(bx / SS) * TT * (DD / 4);

    // hoist the p/L division: within a row p spans < 256 << L slots
    const int bo0 = rs / L;
    const int t0  = rs - bo0 * L;

    for (int wb = wid * 4; wb < count; wb += 32) {
        float  lam[4];
        float4 a[4], c[4];
        int    vv[4], bo_[4], t_[4];
        #pragma unroll
        for (int k = 0; k < 4; k++) {
            const int w = wb + k;
            bool ok = (w < count);
            const float ws  = __fdiv_rn((float)w, sc);
            const float ifl = floorf(ws);
            lam[k] = ws - ifl;
            int i0 = (int)ifl + off;
            i0 = min(max(i0, 0), TT - 1);
            const int i1 = min(i0 + 1, TT - 1);
            int t = t0 + w, bo = bo0;
            if (t >= L) { t -= L; bo++; }
            if (t >= L) { t -= L; bo++; }   // safe for L >= 128 (actual L ~1700)
            ok = ok && (bo < BB) && (t < OUT_T);
            vv[k] = ok; bo_[k] = bo; t_[k] = t;
            if (ok) {
                a[k] = xb[i0 * (DD / 4) + lane];
                c[k] = xb[i1 * (DD / 4) + lane];
            }
        }
        #pragma unroll
        for (int k = 0; k < 4; k++) {
            if (vv[k]) {
                const float l = lam[k], m = 1.0f - l;
                float4 y;
                y.x = m * a[k].x + l * c[k].x;
                y.y = m * a[k].y + l * c[k].y;
                y.z = m * a[k].z + l * c[k].z;
                y.w = m * a[k].w + l * c[k].w;
                ((float4*)out)[((size_t)bo_[k] * OUT_T + t_[k]) * (DD / 4) + lane] = y;
            }
        }
    }
}

// ---------------------------------------------------------------------------
extern "C" void kernel_launch(void* const* d_in, const int* in_sizes, int n_in,
                              void* d_out, int out_size) {
    const float* x           = (const float*)d_in[0];
    const float* scales      = (const float*)d_in[1];
    const int*   len_seq     = (const int*)d_in[2];
    const int*   len_seg_raw = (const int*)d_in[3];
    float*       out         = (float*)d_out;

    k_prep<<<1, 1024>>>(scales, len_seq, len_seg_raw);
    k_main<<<RR + ZBLK, 256>>>(x, scales, out);
}

// round 7
// speedup vs baseline: 1.6000x; 1.1533x over previous
#include <cuda_runtime.h>

#define RR 1040      // B*S segment rows
#define SS 65        // segments per batch
#define BB 16        // batch
#define DD 128       // feature dim
#define WW 256       // candidate positions per segment
#define TT 2176      // MAX_LEN_PAD (x time dim)
#define OUT_T 2048   // MAX_LEN_SEQ
#define NMAIN 888    // main gather blocks (8 warps x 4 slots = 28416 slots/sweep)
#define ZBLK 512     // zero-fill blocks appended to the grid

// Scratch (allocation-free requirement -> __device__ globals)
__device__ int  g_rowstart[RR + 1];   // exclusive prefix of counts; [RR] = total
__device__ int4 g_info[RR];           // {sc bits, seg offset, x base (float4), rowstart}
__device__ int  g_meta[2];            // [0]=total, [1]=L

// ---------------------------------------------------------------------------
// k_prep: ONE block, 1024 threads.
//   - per-batch segment offsets via warp-per-batch shuffle scan (3x32 chunks)
//   - per-row masked count via 8-step binary search with the EXACT fp32
//     predicate (__fdiv_rn is monotone in the numerator; thresholds are
//     integer-valued floats, so floor(w/sc) < lim <=> w/sc < lim)
//   - block-wide exclusive scan -> rowstart, total, L = total // B
// ---------------------------------------------------------------------------
__global__ void __launch_bounds__(1024) k_prep(const float* __restrict__ scales,
                                               const int*   __restrict__ len_seq,
                                               const int*   __restrict__ len_seg_raw) {
    __shared__ int sseg[RR];
    __shared__ int soff[RR];
    __shared__ int s_wsum[32];
    __shared__ int s_wbase[32];
    const int tid  = threadIdx.x;
    const int lane = tid & 31;
    const int wid  = tid >> 5;

    for (int i = tid; i < RR; i += 1024) sseg[i] = len_seg_raw[i] + 32; // +MIN_LEN_SEG
    __syncthreads();

    if (wid < BB) {                      // warp-per-batch exclusive scan of 65 seg lens
        const int base = wid * SS;
        int carry = 0;
        #pragma unroll
        for (int c = 0; c < 3; c++) {
            const int s = c * 32 + lane;
            int v = (s < SS) ? sseg[base + s] : 0;
            int inc = v;
            #pragma unroll
            for (int d = 1; d < 32; d <<= 1) {
                const int n = __shfl_up_sync(0xffffffffu, inc, d);
                if (lane >= d) inc += n;
            }
            if (s < SS) soff[base + s] = carry + inc - v;
            carry += __shfl_sync(0xffffffffu, inc, 31);
        }
    }
    __syncthreads();

    // Two ordered rows per thread -> counts, local scan.
    int cnt[2], loc[2];
    int run = 0;
    #pragma unroll
    for (int j = 0; j < 2; j++) {
        const int r = tid * 2 + j;
        int c = 0;
        if (r < RR) {
            const float sc  = scales[r] + 0.5f;
            const int   off = soff[r];
            const int   ls  = len_seq[r / SS];
            const float lim = fminf((float)(sseg[r] - 1),
                                    (float)(ls - 1) - (float)off);
            int lo = 0, hi = WW;         // pred(w) = __fdiv_rn(w,sc) < lim, prefix-true
            #pragma unroll
            for (int it = 0; it < 8; it++) {
                const int mid = (lo + hi) >> 1;
                if (__fdiv_rn((float)mid, sc) < lim) lo = mid + 1; else hi = mid;
            }
            c = lo;
        }
        loc[j] = run; run += c; cnt[j] = c;
    }
    int inc = run;
    #pragma unroll
    for (int d = 1; d < 32; d <<= 1) {
        const int n = __shfl_up_sync(0xffffffffu, inc, d);
        if (lane >= d) inc += n;
    }
    const int texcl = inc - run;
    if (lane == 31) s_wsum[wid] = inc;
    __syncthreads();
    if (tid == 0) {
        int acc = 0;
        #pragma unroll
        for (int i = 0; i < 32; i++) { s_wbase[i] = acc; acc += s_wsum[i]; }
        g_meta[0] = acc;
        g_meta[1] = acc / BB;            // L = total // B
        g_rowstart[RR] = acc;
    }
    __syncthreads();
    const int base = s_wbase[wid] + texcl;
    #pragma unroll
    for (int j = 0; j < 2; j++) {
        const int r = tid * 2 + j;
        if (r < RR) {
            const int rs = base + loc[j];
            g_rowstart[r] = rs;
            g_info[r] = make_int4(__float_as_int(scales[r] + 0.5f),
                                  soff[r],
                                  (r / SS) * TT * (DD / 4),
                                  rs);
        }
    }
}

// ---------------------------------------------------------------------------
// k_main: blocks [0, NMAIN) grid-stride over the CONTIGUOUS compacted slot
// space p in [0,total). Warp claims 4 consecutive slots; row found by binary
// search in smem rowstart (uniform across warp), then bounded forward walk.
// Blocks [NMAIN, NMAIN+ZBLK) zero-fill the t >= L tail (out is poisoned).
// ---------------------------------------------------------------------------
__global__ void __launch_bounds__(256)
k_main(const float* __restrict__ x,
       float* __restrict__ out) {
    const int bx = blockIdx.x;
    const int L  = g_meta[1];

    if (bx >= NMAIN) {                   // ---- zero-fill tail ----
        if (L >= OUT_T || L <= 0) return;
        const unsigned base = (unsigned)(bx - NMAIN) * 256u + threadIdx.x;
        const float4 z = make_float4(0.f, 0.f, 0.f, 0.f);
        #pragma unroll
        for (int j = 0; j < 8; j++) {
            const unsigned i = base + (unsigned)j * (ZBLK * 256u); // 1,048,576 float4
            const int t = (int)((i >> 5) & (OUT_T - 1));           // 32 float4 per row
            if (t >= L) ((float4*)out)[i] = z;
        }
        return;
    }

    __shared__ int s_rs[RR + 1];
    for (int i = threadIdx.x; i < RR + 1; i += 256) s_rs[i] = g_rowstart[i];
    __syncthreads();
    const int total = s_rs[RR];
    if (L <= 0) return;

    const int lane = threadIdx.x & 31;
    const int gw   = bx * 8 + (threadIdx.x >> 5);     // global warp id
    const float4* __restrict__ x4 = (const float4*)x;

    for (int p0 = gw * 4; p0 < total; p0 += NMAIN * 8 * 4) {
        // row of p0: largest r with rowstart[r] <= p0 (upper-bound skips 0-rows)
        int lo = 0, hi = RR;
        #pragma unroll
        for (int it = 0; it < 11; it++) {
            const int mid = (lo + hi + 1) >> 1;
            if (s_rs[mid] <= p0) lo = mid; else hi = mid - 1;
        }
        int r = lo;
        const int bo0 = p0 / L;
        const int t0  = p0 - bo0 * L;

        float  lam[4];
        float4 a[4], c[4];
        int    vv[4], oidx[4];
        #pragma unroll
        for (int k = 0; k < 4; k++) {
            const int p = p0 + k;
            bool ok = (p < total);
            if (ok) { while (p >= s_rs[r + 1]) r++; }
            const int4 info = g_info[r];
            const float sc = __int_as_float(info.x);
            const int   w  = p - info.w;
            const float ws  = __fdiv_rn((float)w, sc);
            const float ifl = floorf(ws);
            lam[k] = ws - ifl;
            int i0 = (int)ifl + info.y;
            i0 = min(max(i0, 0), TT - 1);
            const int i1 = min(i0 + 1, TT - 1);
            int t = t0 + k, bo = bo0;
            if (t >= L) { t -= L; bo++; }            // k < 4 << L
            ok = ok && (bo < BB) && (t < OUT_T);
            vv[k] = ok;
            oidx[k] = (bo * OUT_T + t) * (DD / 4) + lane;
            if (ok) {
                a[k] = x4[info.z + i0 * (DD / 4) + lane];
                c[k] = x4[info.z + i1 * (DD / 4) + lane];
            }
        }
        #pragma unroll
        for (int k = 0; k < 4; k++) {
            if (vv[k]) {
                const float l = lam[k], m = 1.0f - l;
                float4 y;
                y.x = m * a[k].x + l * c[k].x;
                y.y = m * a[k].y + l * c[k].y;
                y.z = m * a[k].z + l * c[k].z;
                y.w = m * a[k].w + l * c[k].w;
                ((float4*)out)[oidx[k]] = y;
            }
        }
    }
}

// ---------------------------------------------------------------------------
extern "C" void kernel_launch(void* const* d_in, const int* in_sizes, int n_in,
                              void* d_out, int out_size) {
    const float* x           = (const float*)d_in[0];
    const float* scales      = (const float*)d_in[1];
    const int*   len_seq     = (const int*)d_in[2];
    const int*   len_seg_raw = (const int*)d_in[3];
    float*       out         = (float*)d_out;

    k_prep<<<1, 1024>>>(scales, len_seq, len_seg_raw);
    k_main<<<NMAIN + ZBLK, 256>>>(x, out);
}